// round 3
// baseline (speedup 1.0000x reference)
#include <cuda_runtime.h>
#include <cstdint>
#include <cstdio>

#define B_  128
#define S_  50
#define T_  32
#define TQ_ 32
#define H_  256
#define V_  50257
#define G3  768

typedef unsigned long long ull;

// ---------------- scratch (device globals; no allocation) ----------------
__device__ float g_ctx [B_*S_*H_];
__device__ float g_qemb[B_*TQ_*H_];
__device__ float g_gif [B_*S_*G3];
__device__ float g_gib [B_*S_*G3];
__device__ float g_giq [B_*TQ_*G3];
__device__ float g_outf[B_*S_*H_];
__device__ float g_outb[B_*S_*H_];
__device__ float g_q   [B_*H_];
__device__ float g_af  [B_*H_];

// ---------------- helpers ----------------
__device__ __forceinline__ float sigmoidf_(float x){ return 1.0f/(1.0f+expf(-x)); }

__device__ __forceinline__ ull pack2_(float lo, float hi){
    ull r; asm("mov.b64 %0, {%1, %2};" : "=l"(r) : "f"(lo), "f"(hi)); return r;
}
__device__ __forceinline__ ull dup2_(float v){
    ull r; asm("mov.b64 %0, {%1, %1};" : "=l"(r) : "f"(v)); return r;
}
__device__ __forceinline__ void fma2_(ull& d, ull a, ull b){
    asm("fma.rn.f32x2 %0, %1, %2, %0;" : "+l"(d) : "l"(a), "l"(b));
}
__device__ __forceinline__ void add2_(ull& d, ull o){
    asm("add.rn.f32x2 %0, %0, %1;" : "+l"(d) : "l"(o));
}
__device__ __forceinline__ float2 unpack2_(ull v){
    float2 r; asm("mov.b64 {%0, %1}, %2;" : "=f"(r.x), "=f"(r.y) : "l"(v)); return r;
}
__device__ __forceinline__ unsigned smem_u32_(const void* p){
    unsigned r;
    asm("{ .reg .u64 t; cvta.to.shared.u64 t, %1; cvt.u32.u64 %0, t; }" : "=r"(r) : "l"(p));
    return r;
}
__device__ __forceinline__ unsigned mapa_(unsigned laddr, unsigned rank){
    unsigned r;
    asm("mapa.shared::cluster.u32 %0, %1, %2;" : "=r"(r) : "r"(laddr), "r"(rank));
    return r;
}
__device__ __forceinline__ void st_cluster_v2_(unsigned addr, float a, float b){
    asm volatile("st.shared::cluster.v2.f32 [%0], {%1,%2};" :: "r"(addr), "f"(a), "f"(b) : "memory");
}
__device__ __forceinline__ void cluster_arrive_(){
    asm volatile("barrier.cluster.arrive.aligned;" ::: "memory");
}
__device__ __forceinline__ void cluster_wait_(){
    asm volatile("barrier.cluster.wait.aligned;" ::: "memory");
}
__device__ __forceinline__ unsigned ctarank_(){
    unsigned r; asm("mov.u32 %0, %%cluster_ctarank;" : "=r"(r)); return r;
}

// ---------------- 1) embedding + position encoding ----------------
__global__ void embed_pe_kernel(const int* __restrict__ ctx, const float* __restrict__ emb){
    int bs = blockIdx.x;          // b*S_ + s
    int h  = threadIdx.x;         // 0..255
    __shared__ int ids[T_];
    if (h < T_) ids[h] = ctx[bs*T_ + h];
    __syncthreads();
    float e = (float)h * (1.0f/255.0f);
    float acc = 0.f;
#pragma unroll
    for (int t = 0; t < T_; t++){
        float s = (float)t * (1.0f/31.0f);
        float l = 1.0f - s - e*(1.0f - 2.0f*s);
        acc += emb[(size_t)ids[t]*H_ + h] * l;
    }
    g_ctx[(size_t)bs*H_ + h] = acc;
}

__global__ void qemb_kernel(const int* __restrict__ q, const float* __restrict__ emb){
    int i = blockIdx.x;           // b*TQ_ + t
    int h = threadIdx.x;
    g_qemb[(size_t)i*H_ + h] = emb[(size_t)q[i]*H_ + h];
}

// ---------------- 2) GEMM core with packed f32x2 FMAs ----------------
// C[m,n] = sum_k A[m,k] * W[n,k] + bias[n]; K = 256. Tile 128(m) x 64(n).
__device__ __forceinline__ void gemm_body(const float* __restrict__ A,
                                          const float* __restrict__ W,
                                          const float* __restrict__ bias,
                                          float* __restrict__ C,
                                          int N, int bm, int bn)
{
    __shared__ float As[32][132];
    __shared__ float Bs[32][68];
    int tid = threadIdx.x;
    int tx = tid & 15, ty = tid >> 4;

    ull acc[4][4];
#pragma unroll
    for (int i = 0; i < 4; i++)
#pragma unroll
        for (int j = 0; j < 4; j++) acc[i][j] = 0ull;

    for (int k0 = 0; k0 < 256; k0 += 32){
#pragma unroll
        for (int i = 0; i < 4; i++){
            int lin = tid + i*256;
            int row = lin >> 3, kk = (lin & 7) << 2;
            float4 v = *(const float4*)(A + (size_t)(bm+row)*256 + k0 + kk);
            As[kk  ][row] = v.x; As[kk+1][row] = v.y;
            As[kk+2][row] = v.z; As[kk+3][row] = v.w;
        }
#pragma unroll
        for (int i = 0; i < 2; i++){
            int lin = tid + i*256;
            int row = lin >> 3, kk = (lin & 7) << 2;
            int n = bn + row;
            float4 v = make_float4(0.f,0.f,0.f,0.f);
            if (n < N) v = *(const float4*)(W + (size_t)n*256 + k0 + kk);
            Bs[kk  ][row] = v.x; Bs[kk+1][row] = v.y;
            Bs[kk+2][row] = v.z; Bs[kk+3][row] = v.w;
        }
        __syncthreads();
#pragma unroll
        for (int k = 0; k < 32; k++){
            float4 a0 = *(const float4*)(&As[k][ty*8]);
            float4 a1 = *(const float4*)(&As[k][ty*8+4]);
            float4 bv = *(const float4*)(&Bs[k][tx*4]);
            ull ap0 = pack2_(a0.x, a0.y);
            ull ap1 = pack2_(a0.z, a0.w);
            ull ap2 = pack2_(a1.x, a1.y);
            ull ap3 = pack2_(a1.z, a1.w);
            ull bd0 = dup2_(bv.x), bd1 = dup2_(bv.y), bd2 = dup2_(bv.z), bd3 = dup2_(bv.w);
            fma2_(acc[0][0], ap0, bd0); fma2_(acc[0][1], ap0, bd1);
            fma2_(acc[0][2], ap0, bd2); fma2_(acc[0][3], ap0, bd3);
            fma2_(acc[1][0], ap1, bd0); fma2_(acc[1][1], ap1, bd1);
            fma2_(acc[1][2], ap1, bd2); fma2_(acc[1][3], ap1, bd3);
            fma2_(acc[2][0], ap2, bd0); fma2_(acc[2][1], ap2, bd1);
            fma2_(acc[2][2], ap2, bd2); fma2_(acc[2][3], ap2, bd3);
            fma2_(acc[3][0], ap3, bd0); fma2_(acc[3][1], ap3, bd1);
            fma2_(acc[3][2], ap3, bd2); fma2_(acc[3][3], ap3, bd3);
        }
        __syncthreads();
    }
#pragma unroll
    for (int ip = 0; ip < 4; ip++){
        int m = bm + ty*8 + ip*2;
#pragma unroll
        for (int j = 0; j < 4; j++){
            int n = bn + tx*4 + j;
            if (n < N){
                float2 v = unpack2_(acc[ip][j]);
                float bb = bias[n];
                C[(size_t)m*N + n]       = v.x + bb;
                C[(size_t)(m+1)*N + n]   = v.y + bb;
            }
        }
    }
}

// Fused kernel for the three input-gate GEMMs (z selects the problem)
__global__ __launch_bounds__(256) void gemm3_kernel(
    const float* A0, const float* W0, const float* c0, float* C0, int M0,
    const float* A1, const float* W1, const float* c1, float* C1, int M1,
    const float* A2, const float* W2, const float* c2, float* C2, int M2)
{
    const float *A, *W, *cb; float* C; int M;
    if (blockIdx.z == 0){ A=A0; W=W0; cb=c0; C=C0; M=M0; }
    else if (blockIdx.z == 1){ A=A1; W=W1; cb=c1; C=C1; M=M1; }
    else { A=A2; W=W2; cb=c2; C=C2; M=M2; }
    int bm = blockIdx.x * 128;
    if (bm >= M) return;
    gemm_body(A, W, cb, C, G3, bm, blockIdx.y * 64);
}

__global__ __launch_bounds__(256) void gemm_atb(const float* __restrict__ A,
                                                const float* __restrict__ W,
                                                const float* __restrict__ bias,
                                                float* __restrict__ C, int N)
{
    gemm_body(A, W, bias, C, N, blockIdx.x * 128, blockIdx.y * 64);
}

// ---------------- 3) GRU recurrences ----------------
// Cluster of 4 CTAs; CTA owns 64 hidden j (192 Whh rows, k-major in smem).
// 24 clusters: chains f(0..7), b(8..15), q(16..23); 16 batches per cluster.
// Thread = (jp: 32 j-pairs, bg: 4 batch groups, ks: 2 k-slices of 128).
//   tid = jp*8 + bg*2 + ks  -> warp = 4 jp x 4 bg x 2 ks (broadcast-friendly LDS)
// Per k: 3 broadcast LDS.64 (w j-pairs), 1 broadcast LDS.128 (h 4 batches),
//        12 FFMA2. k-partials combined with one shfl_xor(1).
#define GRU_CL_B   16
#define GRU_WT_ST  194
#define GRU_SMEM_FLOATS (256*GRU_WT_ST + 2*256*GRU_CL_B)
#define GRU_SMEM_BYTES  (GRU_SMEM_FLOATS*4)

__global__ void __cluster_dims__(4,1,1) __launch_bounds__(256,1)
gru_kernel(const float* __restrict__ Whh_f, const float* __restrict__ Whh_b, const float* __restrict__ Whh_q,
           const float* __restrict__ bhh_f, const float* __restrict__ bhh_b, const float* __restrict__ bhh_q)
{
    extern __shared__ float sm[];
    float* Wt   = sm;                       // [256 k][194]  (rows: g*64 + j)
    float* hbuf = sm + 256*GRU_WT_ST;       // [2][256 j][16 b]

    int tid = threadIdx.x;
    unsigned rank = ctarank_();
    int cid   = blockIdx.x >> 2;
    int chain = cid >> 3;                   // 0=f, 1=b, 2=q
    int b0    = (cid & 7) * GRU_CL_B;

    const float *Whh, *bhh, *gi;
    float* outp;
    int steps;
    if (chain == 0){ Whh = Whh_f; bhh = bhh_f; gi = g_gif; outp = g_outf; steps = S_;  }
    else if (chain == 1){ Whh = Whh_b; bhh = bhh_b; gi = g_gib; outp = g_outb; steps = S_;  }
    else { Whh = Whh_q; bhh = bhh_q; gi = g_giq; outp = g_q;    steps = TQ_; }

    // load Whh slice transposed: Wt[k][g*64+jj] = Whh[g*256 + rank*64 + jj][k], k = tid
    {
#pragma unroll 4
        for (int rr = 0; rr < 192; rr++){
            int g = rr >> 6, jj = rr & 63;
            Wt[tid*GRU_WT_ST + rr] = Whh[((size_t)(g*256 + (int)rank*64 + jj))*256 + tid];
        }
        for (int i = tid; i < 2*256*GRU_CL_B; i += 256) hbuf[256*GRU_WT_ST - 256*GRU_WT_ST + i + 0] = 0.f, hbuf[i] = 0.f;
    }

    int ks = tid & 1;
    int bg = (tid >> 1) & 3;
    int jp = tid >> 3;                      // 0..31
    int j0 = jp*2;
    int jglob0 = (int)rank*64 + j0;

    // peer hbuf base addresses (mapa hoisted out of the loop)
    unsigned hb_l = smem_u32_(hbuf);
    unsigned peer0 = mapa_(hb_l, 0), peer1 = mapa_(hb_l, 1);
    unsigned peer2 = mapa_(hb_l, 2), peer3 = mapa_(hb_l, 3);

    float2 br2 = *(const float2*)(bhh       + jglob0);
    float2 bz2 = *(const float2*)(bhh + 256 + jglob0);
    float2 bn2 = *(const float2*)(bhh + 512 + jglob0);

    int bb0 = b0 + bg*4 + ks*2;             // this thread's 2 batches: bb0, bb0+1
    float hp00 = 0.f, hp01 = 0.f, hp10 = 0.f, hp11 = 0.f;  // hp[b][j]

    const float* wbase = Wt + ks*128*GRU_WT_ST + j0;
    const float* hbase = hbuf + ks*128*GRU_CL_B + bg*4;

    cluster_arrive_();

    // prefetch gi for step 0
    float2 gr0, gz0, gn0, gr1, gz1, gn1;
    {
        int pos = (chain == 1) ? (S_ - 1) : 0;
        const float* p0 = gi + ((size_t)bb0    *steps + pos)*G3 + jglob0;
        const float* p1 = gi + ((size_t)(bb0+1)*steps + pos)*G3 + jglob0;
        gr0 = *(const float2*)(p0); gz0 = *(const float2*)(p0+256); gn0 = *(const float2*)(p0+512);
        gr1 = *(const float2*)(p1); gz1 = *(const float2*)(p1+256); gn1 = *(const float2*)(p1+512);
    }
    cluster_wait_();

    for (int step = 0; step < steps; step++){
        int cur = step & 1, nxt = cur ^ 1;
        int pos = (chain == 1) ? (S_ - 1 - step) : step;

        // matvec over this thread's 128-k slice
        ull aR[4] = {0,0,0,0}, aZ[4] = {0,0,0,0}, aN[4] = {0,0,0,0};
        const float* wp = wbase;
        const float* hq = hbase + cur*(256*GRU_CL_B);
#pragma unroll 4
        for (int k = 0; k < 128; k++){
            ull wr = *(const ull*)(wp);
            ull wz = *(const ull*)(wp + 64);
            ull wn = *(const ull*)(wp + 128);
            float4 h4 = *(const float4*)(hq);
            ull hd0 = dup2_(h4.x), hd1 = dup2_(h4.y), hd2 = dup2_(h4.z), hd3 = dup2_(h4.w);
            fma2_(aR[0], wr, hd0); fma2_(aR[1], wr, hd1); fma2_(aR[2], wr, hd2); fma2_(aR[3], wr, hd3);
            fma2_(aZ[0], wz, hd0); fma2_(aZ[1], wz, hd1); fma2_(aZ[2], wz, hd2); fma2_(aZ[3], wz, hd3);
            fma2_(aN[0], wn, hd0); fma2_(aN[1], wn, hd1); fma2_(aN[2], wn, hd2); fma2_(aN[3], wn, hd3);
            wp += GRU_WT_ST; hq += GRU_CL_B;
        }
        // combine k-slices (lanes differ in ks = bit 0)
#pragma unroll
        for (int i = 0; i < 4; i++){
            add2_(aR[i], __shfl_xor_sync(0xffffffffu, aR[i], 1));
            add2_(aZ[i], __shfl_xor_sync(0xffffffffu, aZ[i], 1));
            add2_(aN[i], __shfl_xor_sync(0xffffffffu, aN[i], 1));
        }

        // epilogue for this thread's 2 batches (bb0, bb0+1) x 2 j
        int ai = ks*2;
        float2 Ar0 = unpack2_(aR[ai]),   Az0 = unpack2_(aZ[ai]),   An0 = unpack2_(aN[ai]);
        float2 Ar1 = unpack2_(aR[ai+1]), Az1 = unpack2_(aZ[ai+1]), An1 = unpack2_(aN[ai+1]);

        float r00 = sigmoidf_(gr0.x + Ar0.x + br2.x);
        float z00 = sigmoidf_(gz0.x + Az0.x + bz2.x);
        float n00 = tanhf   (gn0.x + r00*(An0.x + bn2.x));
        float h00 = (1.f - z00)*n00 + z00*hp00; hp00 = h00;
        float r01 = sigmoidf_(gr0.y + Ar0.y + br2.y);
        float z01 = sigmoidf_(gz0.y + Az0.y + bz2.y);
        float n01 = tanhf   (gn0.y + r01*(An0.y + bn2.y));
        float h01v = (1.f - z01)*n01 + z01*hp01; hp01 = h01v;

        float r10 = sigmoidf_(gr1.x + Ar1.x + br2.x);
        float z10 = sigmoidf_(gz1.x + Az1.x + bz2.x);
        float n10 = tanhf   (gn1.x + r10*(An1.x + bn2.x));
        float h10 = (1.f - z10)*n10 + z10*hp10; hp10 = h10;
        float r11 = sigmoidf_(gr1.y + Ar1.y + br2.y);
        float z11 = sigmoidf_(gz1.y + Az1.y + bz2.y);
        float n11 = tanhf   (gn1.y + r11*(An1.y + bn2.y));
        float h11v = (1.f - z11)*n11 + z11*hp11; hp11 = h11v;

        // write outputs
        if (chain == 2){
            if (step == steps - 1){
                *(float2*)(outp + (size_t)bb0*H_ + jglob0)     = make_float2(h00, h01v);
                *(float2*)(outp + (size_t)(bb0+1)*H_ + jglob0) = make_float2(h10, h11v);
            }
        } else {
            *(float2*)(outp + ((size_t)bb0*S_ + pos)*H_ + jglob0)     = make_float2(h00, h01v);
            *(float2*)(outp + ((size_t)(bb0+1)*S_ + pos)*H_ + jglob0) = make_float2(h10, h11v);
        }

        // broadcast h to all 4 CTAs' hbuf[nxt]: [j][batch] pairs along batch
        {
            unsigned off0 = (unsigned)(((nxt*256 + jglob0  )*GRU_CL_B + bg*4 + ks*2)*4);
            unsigned off1 = (unsigned)(((nxt*256 + jglob0+1)*GRU_CL_B + bg*4 + ks*2)*4);
            st_cluster_v2_(peer0 + off0, h00, h10);
            st_cluster_v2_(peer0 + off1, h01v, h11v);
            st_cluster_v2_(peer1 + off0, h00, h10);
            st_cluster_v2_(peer1 + off1, h01v, h11v);
            st_cluster_v2_(peer2 + off0, h00, h10);
            st_cluster_v2_(peer2 + off1, h01v, h11v);
            st_cluster_v2_(peer3 + off0, h00, h10);
            st_cluster_v2_(peer3 + off1, h01v, h11v);
        }
        cluster_arrive_();

        // prefetch gi for next step (overlaps peer skew)
        if (step + 1 < steps){
            int np = (chain == 1) ? (S_ - 2 - step) : (step + 1);
            const float* p0 = gi + ((size_t)bb0    *steps + np)*G3 + jglob0;
            const float* p1 = gi + ((size_t)(bb0+1)*steps + np)*G3 + jglob0;
            gr0 = *(const float2*)(p0); gz0 = *(const float2*)(p0+256); gn0 = *(const float2*)(p0+512);
            gr1 = *(const float2*)(p1); gz1 = *(const float2*)(p1+256); gn1 = *(const float2*)(p1+512);
        }
        cluster_wait_();
    }
}

// ---------------- 4) attention + read + tanh(q*read) ----------------
__global__ void attn_kernel(){
    int b = blockIdx.x, h = threadIdx.x;
    __shared__ float en[S_];
    __shared__ float red[8];
    float qh = g_q[(size_t)b*H_ + h];
    int lane = h & 31, wid = h >> 5;
    for (int s = 0; s < S_; s++){
        float f = g_outf[((size_t)b*S_ + s)*H_ + h] + g_outb[((size_t)b*S_ + s)*H_ + h];
        float p = f * qh;
#pragma unroll
        for (int o = 16; o; o >>= 1) p += __shfl_xor_sync(0xffffffffu, p, o);
        if (lane == 0) red[wid] = p;
        __syncthreads();
        if (h < 8){
            float t = red[h];
            t += __shfl_xor_sync(0xffu, t, 4);
            t += __shfl_xor_sync(0xffu, t, 2);
            t += __shfl_xor_sync(0xffu, t, 1);
            if (h == 0) en[s] = t;
        }
        __syncthreads();
    }
    float mx = -1e30f;
    for (int s = 0; s < S_; s++) mx = fmaxf(mx, en[s]);
    float sum = 0.f;
    for (int s = 0; s < S_; s++) sum += expf(en[s] - mx);
    float inv = 1.f / sum;
    float rd = 0.f;
    for (int s = 0; s < S_; s++){
        float a = expf(en[s] - mx) * inv;
        rd += a * (g_outf[((size_t)b*S_ + s)*H_ + h] + g_outb[((size_t)b*S_ + s)*H_ + h]);
    }
    g_af[(size_t)b*H_ + h] = tanhf(qh * rd);
}

// ---------------- launch ----------------
extern "C" void kernel_launch(void* const* d_in, const int* in_sizes, int n_in,
                              void* d_out, int out_size)
{
    const int*   contexts  = (const int*)  d_in[0];
    const int*   questions = (const int*)  d_in[1];
    const float* emb       = (const float*)d_in[2];
    const float* Wih_f     = (const float*)d_in[3];
    const float* Whh_f     = (const float*)d_in[4];
    const float* bih_f     = (const float*)d_in[5];
    const float* bhh_f     = (const float*)d_in[6];
    const float* Wih_b     = (const float*)d_in[7];
    const float* Whh_b     = (const float*)d_in[8];
    const float* bih_b     = (const float*)d_in[9];
    const float* bhh_b     = (const float*)d_in[10];
    const float* Wih_q     = (const float*)d_in[11];
    const float* Whh_q     = (const float*)d_in[12];
    const float* bih_q     = (const float*)d_in[13];
    const float* bhh_q     = (const float*)d_in[14];
    const float* Wo        = (const float*)d_in[15];
    const float* bo        = (const float*)d_in[16];
    float* out = (float*)d_out;

    float *p_ctx, *p_qemb, *p_gif, *p_gib, *p_giq, *p_af;
    cudaGetSymbolAddress((void**)&p_ctx,  g_ctx);
    cudaGetSymbolAddress((void**)&p_qemb, g_qemb);
    cudaGetSymbolAddress((void**)&p_gif,  g_gif);
    cudaGetSymbolAddress((void**)&p_gib,  g_gib);
    cudaGetSymbolAddress((void**)&p_giq,  g_giq);
    cudaGetSymbolAddress((void**)&p_af,   g_af);

    cudaFuncSetAttribute(gru_kernel, cudaFuncAttributeMaxDynamicSharedMemorySize, GRU_SMEM_BYTES);

    // 1) embeddings
    embed_pe_kernel<<<B_*S_, 256>>>(contexts, emb);
    qemb_kernel<<<B_*TQ_, 256>>>(questions, emb);

    // 2) all three input-gate GEMMs in one launch (z selects problem)
    gemm3_kernel<<<dim3(B_*S_/128, G3/64, 3), 256>>>(
        p_ctx,  Wih_f, bih_f, p_gif, B_*S_,
        p_ctx,  Wih_b, bih_b, p_gib, B_*S_,
        p_qemb, Wih_q, bih_q, p_giq, B_*TQ_);

    // 3) all three GRU chains concurrently (24 clusters x 4 CTAs)
    gru_kernel<<<96, 256, GRU_SMEM_BYTES>>>(Whh_f, Whh_b, Whh_q, bhh_f, bhh_b, bhh_q);

    // 4) attention + read + tanh
    attn_kernel<<<B_, 256>>>();

    // 5) vocab projection: out = af @ Wo^T + bo
    gemm_atb<<<dim3(1, (V_ + 63)/64), 256>>>(p_af, Wo, bo, out, V_);
}